// round 1
// baseline (speedup 1.0000x reference)
#include <cuda_runtime.h>

// GaussianYOLOLayer: [B, NA*(NC+6), G, G] -> [B, NA*G*G, NC+6]
// B=32, NA=3, NC+6=86, G=76, stride = 608/76 = 8
// Per (b,a): transpose [86, 5776] -> [5776, 86] with per-channel transforms:
//   c==0: (sigmoid(v) + i) * 8
//   c==1: (sigmoid(v) + j) * 8
//   c==2: exp(v) * anchor_w[a]   (anchor/stride * stride = anchor)
//   c==3: exp(v) * anchor_h[a]
//   c>=4: sigmoid(v)

#define GDIM 76
#define GG   (GDIM * GDIM)   // 5776
#define NCH  86
#define TS   128             // spatial positions per tile
#define NANC 3

__device__ __forceinline__ float fsigmoid(float v) {
    return 1.0f / (1.0f + __expf(-v));
}

__global__ __launch_bounds__(256)
void yolo_head_kernel(const float* __restrict__ x, float* __restrict__ out) {
    __shared__ float tile[NCH][TS + 1];

    const int tidx = threadIdx.x;
    const int tblk = blockIdx.x;   // tile index along spatial dim (46 tiles)
    const int a    = blockIdx.y;   // anchor
    const int b    = blockIdx.z;   // batch

    const int p0 = tblk * TS;

    // anchors (already * stride cancels with /stride in reference)
    const float aw = (a == 0) ? 116.0f : (a == 1) ? 156.0f : 373.0f;
    const float ah = (a == 0) ?  90.0f : (a == 1) ? 198.0f : 326.0f;

    const long long ba = (long long)(b * NANC + a);
    const long long in_base = ba * (long long)NCH * GG + p0;

    // ---- load + transform: coalesced along spatial dim ----
    #pragma unroll 4
    for (int t = tidx; t < NCH * TS; t += 256) {
        const int c = t >> 7;        // / TS
        const int s = t & (TS - 1);  // % TS
        const int p = p0 + s;
        float v = 0.0f;
        if (p < GG) {
            v = x[in_base + (long long)c * GG + s];
            if (c == 0) {
                const int i = p % GDIM;
                v = (fsigmoid(v) + (float)i) * 8.0f;
            } else if (c == 1) {
                const int j = p / GDIM;
                v = (fsigmoid(v) + (float)j) * 8.0f;
            } else if (c == 2) {
                v = __expf(v) * aw;
            } else if (c == 3) {
                v = __expf(v) * ah;
            } else {
                v = fsigmoid(v);
            }
        }
        tile[c][s] = v;
    }

    __syncthreads();

    // ---- store: tile output region is contiguous in gmem ----
    const long long out_base = (ba * (long long)GG + p0) * (long long)NCH;
    const int nvalid = min(TS, GG - p0);
    const int total  = nvalid * NCH;

    #pragma unroll 4
    for (int t = tidx; t < total; t += 256) {
        const int s = t / NCH;       // constant div by 86
        const int c = t - s * NCH;
        out[out_base + t] = tile[c][s];
    }
}

extern "C" void kernel_launch(void* const* d_in, const int* in_sizes, int n_in,
                              void* d_out, int out_size) {
    const float* x = (const float*)d_in[0];
    float* out = (float*)d_out;

    const int B = 32;
    const int ntiles = (GG + TS - 1) / TS;  // 46
    dim3 grid(ntiles, NANC, B);
    yolo_head_kernel<<<grid, 256>>>(x, out);
}

// round 2
// speedup vs baseline: 1.9748x; 1.9748x over previous
#include <cuda_runtime.h>

// GaussianYOLOLayer: [B, NA*(NC+6), G, G] -> [B, NA*G*G, NC+6]
// B=32, NA=3, NC+6=86, G=76, stride = 608/76 = 8
// Per (b,a): transpose [86, 5776] -> [5776, 86] with per-channel transforms:
//   c==0: (sigmoid(v) + i) * 8
//   c==1: (sigmoid(v) + j) * 8
//   c==2: exp(v) * anchor_w[a]
//   c==3: exp(v) * anchor_h[a]
//   c>=4: sigmoid(v)

#define GDIM 76
#define GG   5776
#define NCH  86
#define TS   128            // spatial positions per tile
#define NANC 3
#define ROW  128            // words per channel row in smem (== TS, no pad; XOR swizzle)

__device__ __forceinline__ float fsigmoid(float v) {
    return 1.0f / (1.0f + __expf(-v));
}

__global__ __launch_bounds__(256)
void yolo_head_kernel(const float* __restrict__ x, float* __restrict__ out) {
    // XOR-swizzled tile: word(c, s) = c*ROW + (s ^ ((c>>1) & 31))
    // Phase A (write): warp has fixed c -> mask const -> banks = s^m distinct. CF.
    // Phase B (read):  warp has ~fixed s, c0=2j, j consecutive -> mask = j&31 -> CF.
    __shared__ float tile[NCH * ROW];   // 44032 B -> 5 CTAs/SM

    const int tidx = threadIdx.x;
    const int tblk = blockIdx.x;   // 46 tiles along spatial dim
    const int a    = blockIdx.y;   // anchor
    const int b    = blockIdx.z;   // batch

    const int p0     = tblk * TS;
    const int nvalid = min(TS, GG - p0);   // 128, or 16 on last tile (mult of 16)

    const float aw = (a == 0) ? 116.0f : (a == 1) ? 156.0f : 373.0f;
    const float ah = (a == 0) ?  90.0f : (a == 1) ? 198.0f : 326.0f;

    const long long ba = (long long)(b * NANC + a);
    const float4* __restrict__ xin =
        (const float4*)(x + ba * (long long)NCH * GG);
    const int p4 = p0 >> 2;   // p0 is a multiple of 128

    // ---- Phase A: coalesced LDG.128 along spatial dim, transform, swizzled STS ----
    #pragma unroll 3
    for (int t4 = tidx; t4 < NCH * (TS / 4); t4 += 256) {
        const int c = t4 >> 5;        // channel (uniform within warp)
        const int u = t4 & 31;
        const int s = 4 * u;
        if (s < nvalid) {
            float4 v = xin[(long long)c * (GG / 4) + p4 + u];
            float r0, r1, r2, r3;
            if (c >= 4) {
                r0 = fsigmoid(v.x); r1 = fsigmoid(v.y);
                r2 = fsigmoid(v.z); r3 = fsigmoid(v.w);
            } else if (c == 0) {
                const int p = p0 + s;
                int i0 = p % GDIM;
                int i1 = i0 + 1; if (i1 >= GDIM) i1 -= GDIM;
                int i2 = i1 + 1; if (i2 >= GDIM) i2 -= GDIM;
                int i3 = i2 + 1; if (i3 >= GDIM) i3 -= GDIM;
                r0 = (fsigmoid(v.x) + (float)i0) * 8.0f;
                r1 = (fsigmoid(v.y) + (float)i1) * 8.0f;
                r2 = (fsigmoid(v.z) + (float)i2) * 8.0f;
                r3 = (fsigmoid(v.w) + (float)i3) * 8.0f;
            } else if (c == 1) {
                const int p = p0 + s;
                const int j0 = p / GDIM;
                const int i0 = p - j0 * GDIM;
                const int j1 = j0 + ((i0 + 1) >= GDIM ? 1 : 0);
                const int j2 = j0 + ((i0 + 2) >= GDIM ? 1 : 0);
                const int j3 = j0 + ((i0 + 3) >= GDIM ? 1 : 0);
                r0 = (fsigmoid(v.x) + (float)j0) * 8.0f;
                r1 = (fsigmoid(v.y) + (float)j1) * 8.0f;
                r2 = (fsigmoid(v.z) + (float)j2) * 8.0f;
                r3 = (fsigmoid(v.w) + (float)j3) * 8.0f;
            } else if (c == 2) {
                r0 = __expf(v.x) * aw; r1 = __expf(v.y) * aw;
                r2 = __expf(v.z) * aw; r3 = __expf(v.w) * aw;
            } else { // c == 3
                r0 = __expf(v.x) * ah; r1 = __expf(v.y) * ah;
                r2 = __expf(v.z) * ah; r3 = __expf(v.w) * ah;
            }
            const int m    = (c >> 1) & 31;
            const int base = c * ROW;
            tile[base + ((s + 0) ^ m)] = r0;
            tile[base + ((s + 1) ^ m)] = r1;
            tile[base + ((s + 2) ^ m)] = r2;
            tile[base + ((s + 3) ^ m)] = r3;
        }
    }

    __syncthreads();

    // ---- Phase B: swizzled LDS gather, contiguous STG.64 ----
    // output region for this tile is contiguous: nvalid*86 floats = nvalid*43 float2
    const long long out_base = (ba * (long long)GG + p0) * NCH;
    float2* __restrict__ out2 = (float2*)(out + out_base);
    const int total2 = nvalid * (NCH / 2);

    #pragma unroll 4
    for (int t2 = tidx; t2 < total2; t2 += 256) {
        const int s  = t2 / 43;           // magic-div
        const int j  = t2 - s * 43;       // channel pair index, c0 = 2j
        const int sw = s ^ (j & 31);      // matches phase-A mask ((c>>1)&31 == j)
        float2 w;
        w.x = tile[(2 * j    ) * ROW + sw];
        w.y = tile[(2 * j + 1) * ROW + sw];
        out2[t2] = w;
    }
}

extern "C" void kernel_launch(void* const* d_in, const int* in_sizes, int n_in,
                              void* d_out, int out_size) {
    const float* x = (const float*)d_in[0];
    float* out = (float*)d_out;

    const int ntiles = (GG + TS - 1) / TS;  // 46
    dim3 grid(ntiles, NANC, 32);
    yolo_head_kernel<<<grid, 256>>>(x, out);
}

// round 3
// speedup vs baseline: 2.0134x; 1.0195x over previous
#include <cuda_runtime.h>

#define GDIM 76
#define GG   5776
#define NCH  86
#define TS   64
#define NANC 3
#define ROWF 96              // 48 float2 slots per spatial row (swizzled indices 0..47)

__device__ __forceinline__ float fsigmoid(float v) {
    return 1.0f / (1.0f + __expf(-v));
}

__global__ __launch_bounds__(256, 6)
void yolo_head_kernel(const float* __restrict__ x, float* __restrict__ out) {
    // s-major float2-swizzled tile:
    //   slot(s, c) : j=c>>1, idx2 = (j & 48) | ((j ^ ((s>>2)&15)) & 15)
    //   float word = s*ROWF + 2*idx2 + (c&1)
    __shared__ float tile[TS * ROWF];   // 24576 B -> 6 CTAs/SM (147KB)

    const int tidx = threadIdx.x;
    const int tblk = blockIdx.x;
    const int a    = blockIdx.y;
    const int b    = blockIdx.z;

    const int p0     = tblk * TS;
    const int nvalid = min(TS, GG - p0);

    const float aw = (a == 0) ? 116.0f : (a == 1) ? 156.0f : 373.0f;
    const float ah = (a == 0) ?  90.0f : (a == 1) ? 198.0f : 326.0f;

    const long long ba = (long long)(b * NANC + a);
    const float4* __restrict__ xin = (const float4*)(x + ba * (long long)NCH * GG);
    const int p4 = p0 >> 2;

    #pragma unroll 2
    for (int t4 = tidx; t4 < NCH * (TS / 4); t4 += 256) {
        const int c = t4 >> 4;
        const int u = t4 & 15;
        const int s = 4 * u;
        if (s < nvalid) {
            float4 v = xin[(long long)c * (GG / 4) + p4 + u];
            float r0, r1, r2, r3;
            if (c >= 4) {
                r0 = fsigmoid(v.x); r1 = fsigmoid(v.y);
                r2 = fsigmoid(v.z); r3 = fsigmoid(v.w);
            } else if (c == 0) {
                const int p = p0 + s;
                int i0 = p % GDIM;
                int i1 = i0 + 1; if (i1 >= GDIM) i1 -= GDIM;
                int i2 = i1 + 1; if (i2 >= GDIM) i2 -= GDIM;
                int i3 = i2 + 1; if (i3 >= GDIM) i3 -= GDIM;
                r0 = (fsigmoid(v.x) + (float)i0) * 8.0f;
                r1 = (fsigmoid(v.y) + (float)i1) * 8.0f;
                r2 = (fsigmoid(v.z) + (float)i2) * 8.0f;
                r3 = (fsigmoid(v.w) + (float)i3) * 8.0f;
            } else if (c == 1) {
                const int p = p0 + s;
                const int j0 = p / GDIM;
                const int i0 = p - j0 * GDIM;
                const int j1 = j0 + ((i0 + 1) >= GDIM ? 1 : 0);
                const int j2 = j0 + ((i0 + 2) >= GDIM ? 1 : 0);
                const int j3 = j0 + ((i0 + 3) >= GDIM ? 1 : 0);
                r0 = (fsigmoid(v.x) + (float)j0) * 8.0f;
                r1 = (fsigmoid(v.y) + (float)j1) * 8.0f;
                r2 = (fsigmoid(v.z) + (float)j2) * 8.0f;
                r3 = (fsigmoid(v.w) + (float)j3) * 8.0f;
            } else if (c == 2) {
                r0 = __expf(v.x) * aw; r1 = __expf(v.y) * aw;
                r2 = __expf(v.z) * aw; r3 = __expf(v.w) * aw;
            } else {
                r0 = __expf(v.x) * ah; r1 = __expf(v.y) * ah;
                r2 = __expf(v.z) * ah; r3 = __expf(v.w) * ah;
            }
            const int jj  = c >> 1;
            const int par = c & 1;
            // (s+k)>>2 == u for k=0..3 -> swizzle constant per thread
            const int idx2 = (jj & 48) | ((jj ^ u) & 15);
            const int off  = (idx2 << 1) + par;
            tile[(s + 0) * ROWF + off] = r0;
            tile[(s + 1) * ROWF + off] = r1;
            tile[(s + 2) * ROWF + off] = r2;
            tile[(s + 3) * ROWF + off] = r3;
        }
    }

    __syncthreads();

    const long long out_base = (ba * (long long)GG + p0) * NCH;
    float2* __restrict__ out2 = (float2*)(out + out_base);
    const int total2 = nvalid * (NCH / 2);

    #pragma unroll 4
    for (int t2 = tidx; t2 < total2; t2 += 256) {
        const int s = t2 / 43;
        const int j = t2 - s * 43;
        const int m = (s >> 2) & 15;
        const int idx2 = (j & 48) | ((j ^ m) & 15);
        float2 w = *(const float2*)&tile[s * ROWF + (idx2 << 1)];
        out2[t2] = w;
    }
}

extern "C" void kernel_launch(void* const* d_in, const int* in_sizes, int n_in,
                              void* d_out, int out_size) {
    const float* x = (const float*)d_in[0];
    float* out = (float*)d_out;

    const int ntiles = (GG + TS - 1) / TS;  // 91
    dim3 grid(ntiles, NANC, 32);
    yolo_head_kernel<<<grid, 256>>>(x, out);
}

// round 5
// speedup vs baseline: 2.3137x; 1.1491x over previous
#include <cuda_runtime.h>

// GaussianYOLOLayer: [B, NA*(NC+6), G, G] -> [B, NA*G*G, NC+6]
// B=32, NA=3, NC+6=86, G=76, stride=8.
//   c==0: (sigmoid(v)+i)*8   c==1: (sigmoid(v)+j)*8
//   c==2: exp(v)*116|156|373 c==3: exp(v)*90|198|326   c>=4: sigmoid(v)

#define GDIM 76
#define GG   5776
#define NCH  86
#define NJP  43              // channel pairs
#define TS   64              // spatial positions per tile
#define NANC 3
#define ROW2 48              // float2 slots per spatial row (swizzled idx 0..47)

__device__ __forceinline__ float fsigmoid(float v) {
    return 1.0f / (1.0f + __expf(-v));
}

// float2 slot index for (s, channel-pair j):
//   idx2 = (j & 48) | ((j ^ ((s>>2)&15)) & 15)    [KEEP bits 4 and 5 of j!]
__device__ __forceinline__ int slot_idx(int j, int m) {
    return (j & 48) | ((j ^ m) & 15);
}

__global__ __launch_bounds__(256, 7)
void yolo_head_kernel(const float* __restrict__ x, float* __restrict__ out) {
    __shared__ float2 tile2[TS * ROW2];   // 24576 B -> 7 CTAs/SM

    const int tidx = threadIdx.x;
    const int tblk = blockIdx.x;   // 91 spatial tiles
    const int a    = blockIdx.y;
    const int b    = blockIdx.z;

    const int p0     = tblk * TS;
    const int nvalid = min(TS, GG - p0);   // 64, or 16 on last tile

    const float aw = (a == 0) ? 116.0f : (a == 1) ? 156.0f : 373.0f;
    const float ah = (a == 0) ?  90.0f : (a == 1) ? 198.0f : 326.0f;

    const long long ba = (long long)(b * NANC + a);
    const float4* __restrict__ xin = (const float4*)(x + ba * (long long)NCH * GG);
    const int p4 = p0 >> 2;

    // ================= Phase A: paired-channel load + transform + STS.64 ====
    const int u = tidx & 15;        // which float4 along spatial dim
    const int s = u << 2;

    if (s < nvalid) {
        #pragma unroll
        for (int it = 0; it < 3; ++it) {
            const int jj = (tidx >> 4) + 16 * it;   // channel pair, uniform/half-warp
            if (jj < NJP) {
                const int c0 = 2 * jj;
                const float4 vl = xin[(long long)(c0    ) * (GG / 4) + p4 + u];
                const float4 vh = xin[(long long)(c0 + 1) * (GG / 4) + p4 + u];
                float2 r0, r1, r2, r3;   // (lo=c0, hi=c0+1) per s+k
                if (jj >= 2) {
                    r0 = make_float2(fsigmoid(vl.x), fsigmoid(vh.x));
                    r1 = make_float2(fsigmoid(vl.y), fsigmoid(vh.y));
                    r2 = make_float2(fsigmoid(vl.z), fsigmoid(vh.z));
                    r3 = make_float2(fsigmoid(vl.w), fsigmoid(vh.w));
                } else if (jj == 0) {
                    // c0=0: (sig+i)*8 ; c0+1=1: (sig+j)*8
                    const int p  = p0 + s;
                    const int j0 = p / GDIM;
                    const int i0 = p - j0 * GDIM;
                    int i1 = i0 + 1, j1 = j0; if (i1 >= GDIM) { i1 = 0; j1++; }
                    int i2 = i1 + 1, j2 = j1; if (i2 >= GDIM) { i2 = 0; j2++; }
                    int i3 = i2 + 1, j3 = j2; if (i3 >= GDIM) { i3 = 0; j3++; }
                    r0 = make_float2((fsigmoid(vl.x) + (float)i0) * 8.0f,
                                     (fsigmoid(vh.x) + (float)j0) * 8.0f);
                    r1 = make_float2((fsigmoid(vl.y) + (float)i1) * 8.0f,
                                     (fsigmoid(vh.y) + (float)j1) * 8.0f);
                    r2 = make_float2((fsigmoid(vl.z) + (float)i2) * 8.0f,
                                     (fsigmoid(vh.z) + (float)j2) * 8.0f);
                    r3 = make_float2((fsigmoid(vl.w) + (float)i3) * 8.0f,
                                     (fsigmoid(vh.w) + (float)j3) * 8.0f);
                } else { // jj == 1: c=2 (w), c=3 (h)
                    r0 = make_float2(__expf(vl.x) * aw, __expf(vh.x) * ah);
                    r1 = make_float2(__expf(vl.y) * aw, __expf(vh.y) * ah);
                    r2 = make_float2(__expf(vl.z) * aw, __expf(vh.z) * ah);
                    r3 = make_float2(__expf(vl.w) * aw, __expf(vh.w) * ah);
                }
                // (s+k)>>2 == u for k=0..3 -> swizzle mask constant per thread
                const int idx2 = slot_idx(jj, u);
                tile2[(s + 0) * ROW2 + idx2] = r0;
                tile2[(s + 1) * ROW2 + idx2] = r1;
                tile2[(s + 2) * ROW2 + idx2] = r2;
                tile2[(s + 3) * ROW2 + idx2] = r3;
            }
        }
    }

    __syncthreads();

    // ================= Phase B: gather 2x LDS.64 -> STG.128 =================
    // Tile's output region is contiguous: nvalid*86 floats = nvalid*21.5 float4.
    const long long out_base = (ba * (long long)GG + p0) * NCH;
    float4* __restrict__ out4 = (float4*)(out + out_base);
    const int total4 = (nvalid * NJP) >> 1;   // 1376 (full) / 344 (last)

    #pragma unroll 3
    for (int t4 = tidx; t4 < total4; t4 += 256) {
        const int d0 = t4 << 1;          // even float2 index in (s*43 + j) space
        const int sA = d0 / 43;
        const int jA = d0 - sA * 43;
        int jB = jA + 1, sB = sA;
        if (jB == NJP) { jB = 0; sB = sA + 1; }   // row wrap (jA==42 -> sA even)
        const float2 lo = tile2[sA * ROW2 + slot_idx(jA, (sA >> 2) & 15)];
        const float2 hi = tile2[sB * ROW2 + slot_idx(jB, (sB >> 2) & 15)];
        out4[t4] = make_float4(lo.x, lo.y, hi.x, hi.y);
    }
}

extern "C" void kernel_launch(void* const* d_in, const int* in_sizes, int n_in,
                              void* d_out, int out_size) {
    const float* x = (const float*)d_in[0];
    float* out = (float*)d_out;

    const int ntiles = (GG + TS - 1) / TS;  // 91
    dim3 grid(ntiles, NANC, 32);
    yolo_head_kernel<<<grid, 256>>>(x, out);
}